// round 1
// baseline (speedup 1.0000x reference)
#include <cuda_runtime.h>
#include <math.h>

#define N_NODES 50000
#define N_EDGES 800000
#define FMAX 256

// ---------------- scratch (static device allocations; no cudaMalloc) --------
__device__ float g_hA[(size_t)N_NODES * FMAX];
__device__ float g_hB[(size_t)N_NODES * FMAX];
__device__ float g_x1[(size_t)N_NODES * FMAX];
__device__ float g_dinv[N_NODES];
__device__ int   g_deg[N_NODES];
__device__ int   g_off[N_NODES + 1];
__device__ int   g_cur[N_NODES];
__device__ int   g_csrc[N_EDGES];

// ---------------- CSR build --------------------------------------------------
__global__ void k_zero_deg() {
    int i = blockIdx.x * blockDim.x + threadIdx.x;
    if (i < N_NODES) g_deg[i] = 0;
}

__global__ void k_count(const int* __restrict__ dst) {
    int e = blockIdx.x * blockDim.x + threadIdx.x;
    if (e < N_EDGES) atomicAdd(&g_deg[dst[e]], 1);
}

// Single-block exclusive scan of g_deg -> g_off, also writes g_cur and g_dinv.
__global__ void k_scan_dinv() {
    __shared__ int sh[1024];
    __shared__ int s_carry;
    int tid = threadIdx.x;
    if (tid == 0) s_carry = 0;
    __syncthreads();
    for (int base = 0; base < N_NODES; base += 1024) {
        int i = base + tid;
        int v = (i < N_NODES) ? g_deg[i] : 0;
        sh[tid] = v;
        __syncthreads();
        // Hillis-Steele inclusive scan
        for (int ofs = 1; ofs < 1024; ofs <<= 1) {
            int t = (tid >= ofs) ? sh[tid - ofs] : 0;
            __syncthreads();
            sh[tid] += t;
            __syncthreads();
        }
        int incl = sh[tid];
        int carry = s_carry;
        if (i < N_NODES) {
            int start = carry + incl - v;
            g_off[i] = start;
            g_cur[i] = start;
            g_dinv[i] = (v > 0) ? rsqrtf((float)v) : 0.0f;
        }
        __syncthreads();
        if (tid == 1023) s_carry = carry + incl;
        __syncthreads();
    }
    if (tid == 0) g_off[N_NODES] = s_carry;
}

__global__ void k_scatter(const int* __restrict__ src, const int* __restrict__ dst) {
    int e = blockIdx.x * blockDim.x + threadIdx.x;
    if (e < N_EDGES) {
        int p = atomicAdd(&g_cur[dst[e]], 1);
        g_csrc[p] = src[e];
    }
}

// ---------------- SpMM gather: x1 = -dinv .* (A @ (dinv .* h)) ---------------
// One warp per (node, 128-column chunk). Each lane accumulates a float4.
__global__ void k_spmm(const float* __restrict__ hin, int F, float* __restrict__ x1) {
    int node = blockIdx.x * 8 + (threadIdx.x >> 5);
    if (node >= N_NODES) return;
    int lane = threadIdx.x & 31;
    int col = blockIdx.y * 128 + lane * 4;

    float dv = g_dinv[node];
    float4 acc = make_float4(0.f, 0.f, 0.f, 0.f);
    int e0 = g_off[node], e1 = g_off[node + 1];
    for (int e = e0; e < e1; e++) {
        int j = g_csrc[e];
        float dj = g_dinv[j];
        float4 v = *reinterpret_cast<const float4*>(hin + (size_t)j * F + col);
        acc.x += dj * v.x;
        acc.y += dj * v.y;
        acc.z += dj * v.z;
        acc.w += dj * v.w;
    }
    float s = -dv;
    float4 o = make_float4(s * acc.x, s * acc.y, s * acc.z, s * acc.w);
    *reinterpret_cast<float4*>(x1 + (size_t)node * F + col) = o;
}

// ---------------- fused concat GEMM: out = act([h | x1] @ W + b) -------------
// Tiles: BM=128, BN=128, BK=16; 256 threads; 8x8 per thread.
// K-tiles never straddle the concat boundary (16 | F), so each tile selects
// its source pointer (h or x1) once.
#define BM 128
#define BN 128
#define BK 16

__global__ void __launch_bounds__(256) k_gemm(
    const float* __restrict__ A0, const float* __restrict__ A1, int F,
    const float* __restrict__ W, const float* __restrict__ bias,
    float* __restrict__ out, int Nout, int act)
{
    __shared__ float As[BK][BM + 4];
    __shared__ float Bs[BK][BN];

    int tid = threadIdx.x;
    int tx = tid & 15;       // 0..15 -> 8 output cols each
    int ty = tid >> 4;       // 0..15 -> 8 output rows each
    int m0 = blockIdx.x * BM;
    int n0 = blockIdx.y * BN;
    int K = 2 * F;

    float acc[8][8];
#pragma unroll
    for (int i = 0; i < 8; i++)
#pragma unroll
        for (int j = 0; j < 8; j++) acc[i][j] = 0.f;

    // A tile loader mapping: 4 float4s per row, 64 rows per pass, 2 passes
    int a_row = tid >> 2;          // 0..63
    int a_col4 = (tid & 3) * 4;    // 0,4,8,12
    // B tile loader mapping: 32 float4s per k-row, 8 rows per pass, 2 passes
    int b_row = tid >> 5;          // 0..7
    int b_col4 = (tid & 31) * 4;   // 0..124

    for (int k0 = 0; k0 < K; k0 += BK) {
        const float* Asrc = (k0 < F) ? (A0 + k0) : (A1 + (k0 - F));
#pragma unroll
        for (int p = 0; p < 2; p++) {
            int row = a_row + p * 64;
            int m = m0 + row;
            float4 v = (m < N_NODES)
                ? *reinterpret_cast<const float4*>(Asrc + (size_t)m * F + a_col4)
                : make_float4(0.f, 0.f, 0.f, 0.f);
            As[a_col4 + 0][row] = v.x;
            As[a_col4 + 1][row] = v.y;
            As[a_col4 + 2][row] = v.z;
            As[a_col4 + 3][row] = v.w;
        }
#pragma unroll
        for (int p = 0; p < 2; p++) {
            int kr = b_row + p * 8;
            float4 v = *reinterpret_cast<const float4*>(
                W + (size_t)(k0 + kr) * Nout + n0 + b_col4);
            *reinterpret_cast<float4*>(&Bs[kr][b_col4]) = v;
        }
        __syncthreads();

#pragma unroll
        for (int k = 0; k < BK; k++) {
            float a[8], b[8];
#pragma unroll
            for (int i = 0; i < 8; i++) a[i] = As[k][ty * 8 + i];
#pragma unroll
            for (int j = 0; j < 8; j++) b[j] = Bs[k][tx * 8 + j];
#pragma unroll
            for (int i = 0; i < 8; i++)
#pragma unroll
                for (int j = 0; j < 8; j++) acc[i][j] += a[i] * b[j];
        }
        __syncthreads();
    }

#pragma unroll
    for (int i = 0; i < 8; i++) {
        int m = m0 + ty * 8 + i;
        if (m >= N_NODES) continue;
#pragma unroll
        for (int j = 0; j < 8; j += 4) {
            int n = n0 + tx * 8 + j;
            float4 r;
            r.x = acc[i][j + 0] + bias[n + 0];
            r.y = acc[i][j + 1] + bias[n + 1];
            r.z = acc[i][j + 2] + bias[n + 2];
            r.w = acc[i][j + 3] + bias[n + 3];
            if (act) {
                r.x = tanhf(r.x); r.y = tanhf(r.y);
                r.z = tanhf(r.z); r.w = tanhf(r.w);
            }
            *reinterpret_cast<float4*>(out + (size_t)m * Nout + n) = r;
        }
    }
}

// ---------------- launch -----------------------------------------------------
extern "C" void kernel_launch(void* const* d_in, const int* in_sizes, int n_in,
                              void* d_out, int out_size) {
    const float* x  = (const float*)d_in[0];
    const int*   src = (const int*)d_in[1];
    const int*   dst = (const int*)d_in[2];
    const float* W1 = (const float*)d_in[3];
    const float* b1 = (const float*)d_in[4];
    const float* W2 = (const float*)d_in[5];
    const float* b2 = (const float*)d_in[6];
    const float* W3 = (const float*)d_in[7];
    const float* b3 = (const float*)d_in[8];
    float* out = (float*)d_out;

    void *hA_v, *hB_v, *x1_v;
    cudaGetSymbolAddress(&hA_v, g_hA);
    cudaGetSymbolAddress(&hB_v, g_hB);
    cudaGetSymbolAddress(&x1_v, g_x1);
    float* hA = (float*)hA_v;
    float* hB = (float*)hB_v;
    float* x1 = (float*)x1_v;

    // CSR build
    k_zero_deg<<<(N_NODES + 255) / 256, 256>>>();
    k_count<<<(N_EDGES + 255) / 256, 256>>>(dst);
    k_scan_dinv<<<1, 1024>>>();
    k_scatter<<<(N_EDGES + 255) / 256, 256>>>(src, dst);

    auto layer = [&](const float* hin, int F, const float* W, const float* b,
                     float* hout, int Nout, int act) {
        dim3 gs((N_NODES + 7) / 8, F / 128);
        k_spmm<<<gs, 256>>>(hin, F, x1);
        dim3 gg((N_NODES + BM - 1) / BM, Nout / BN);
        k_gemm<<<gg, 256>>>(hin, x1, F, W, b, hout, Nout, act);
    };

    layer(x,  128, W1, b1, hA, 256, 1);
    layer(hA, 256, W2, b2, hB, 256, 1);
    layer(hB, 256, W2, b2, hA, 256, 1);
    layer(hA, 256, W2, b2, hB, 256, 1);
    layer(hB, 256, W3, b3, out, 128, 0);
}

// round 3
// speedup vs baseline: 1.9046x; 1.9046x over previous
#include <cuda_runtime.h>
#include <cuda_bf16.h>
#include <stdint.h>
#include <math.h>

#define MTOT 50000
#define NE   800000

// tcgen05 is an arch-SPECIFIC ("a") feature. Guard it so the plain compute_103
// PTX pass compiles; that pass gets the SIMT fallback body instead.
#if defined(__CUDA_ARCH_FEAT_SM103_ALL) || defined(__CUDA_ARCH_FEAT_SM100_ALL) || \
    defined(__CUDA_ARCH_FEAT_SM101_ALL) || defined(__CUDA_ARCH_FEAT_SM110_ALL)
#define TC_OK 1
#else
#define TC_OK 0
#endif

// ---------------- device scratch (no cudaMalloc) ----------------------------
__device__ __align__(16) __nv_bfloat16 g_AhiA[(size_t)MTOT * 512];
__device__ __align__(16) __nv_bfloat16 g_AloA[(size_t)MTOT * 512];
__device__ __align__(16) __nv_bfloat16 g_AhiB[(size_t)MTOT * 512];
__device__ __align__(16) __nv_bfloat16 g_AloB[(size_t)MTOT * 512];
__device__ __align__(16) __nv_bfloat16 g_Wthi[262144];
__device__ __align__(16) __nv_bfloat16 g_Wtlo[262144];
__device__ float g_dinv[MTOT];
__device__ int   g_deg[MTOT];
__device__ int   g_off[MTOT + 1];
__device__ int   g_cur[MTOT];
__device__ int   g_csrc[NE];

// ---------------- small helpers ---------------------------------------------
__device__ __forceinline__ uint32_t smem_u32(const void* p) {
    uint32_t a;
    asm("{ .reg .u64 t; cvta.to.shared.u64 t, %1; cvt.u32.u64 %0, t; }" : "=r"(a) : "l"(p));
    return a;
}
__device__ __forceinline__ bool elect1() {
    uint32_t p;
    asm volatile("{\n\t.reg .pred p;\n\telect.sync _|p, 0xFFFFFFFF;\n\tselp.b32 %0,1,0,p;\n\t}" : "=r"(p));
    return p != 0;
}
__device__ __forceinline__ void mbar_init(uint32_t mbar, uint32_t cnt) {
    asm volatile("mbarrier.init.shared.b64 [%0], %1;" :: "r"(mbar), "r"(cnt) : "memory");
}
__device__ __forceinline__ void mbar_wait(uint32_t mbar, uint32_t parity) {
    uint32_t done;
    asm volatile("{\n\t.reg .pred p;\n\tmbarrier.try_wait.parity.acquire.cta.shared::cta.b64 p, [%1], %2;\n\tselp.b32 %0,1,0,p;\n\t}"
                 : "=r"(done) : "r"(mbar), "r"(parity) : "memory");
    if (!done) {
        asm volatile("{\n\t.reg .pred P1;\nWL_%=:\n\tmbarrier.try_wait.parity.acquire.cta.shared::cta.b64 P1, [%0], %1, 0x989680;\n\t@P1 bra.uni WD_%=;\n\tbra.uni WL_%=;\nWD_%=:\n\t}"
                     :: "r"(mbar), "r"(parity) : "memory");
    }
}
__device__ __forceinline__ float tanha(float x) {
    float y; asm("tanh.approx.f32 %0, %1;" : "=f"(y) : "f"(x)); return y;
}
__device__ __forceinline__ float bhi(float v) {
    return __bfloat162float(__float2bfloat16_rn(v));
}
__device__ __forceinline__ uint32_t pk2(float a, float b) {
    uint16_t ha = __bfloat16_as_ushort(__float2bfloat16_rn(a));
    uint16_t hb = __bfloat16_as_ushort(__float2bfloat16_rn(b));
    return (uint32_t)ha | ((uint32_t)hb << 16);
}

#if TC_OK
__device__ __forceinline__ uint64_t mk_desc(uint32_t addr) {
    // SW128, version=1(Blackwell), SBO=64, LBO=1, start=addr>>4
    return 0x4000404000010000ULL | ((uint64_t)(addr >> 4) & 0x3FFF);
}
__device__ __forceinline__ void mma_ss_f16(uint32_t d, uint64_t ad, uint64_t bd,
                                           uint32_t idesc, uint32_t en) {
    asm volatile("{\n\t.reg .pred p;\n\tsetp.ne.u32 p, %4, 0;\n\t"
                 "tcgen05.mma.cta_group::1.kind::f16 [%0], %1, %2, %3, {%5,%5,%5,%5}, p;\n\t}"
                 :: "r"(d), "l"(ad), "l"(bd), "r"(idesc), "r"(en), "r"(0u) : "memory");
}
#define LDTM32(r, addr) \
    asm volatile("tcgen05.ld.sync.aligned.32x32b.x32.b32 " \
        "{%0,%1,%2,%3,%4,%5,%6,%7,%8,%9,%10,%11,%12,%13,%14,%15," \
        "%16,%17,%18,%19,%20,%21,%22,%23,%24,%25,%26,%27,%28,%29,%30,%31}, [%32];" \
        : "=r"((r)[0]),"=r"((r)[1]),"=r"((r)[2]),"=r"((r)[3]),"=r"((r)[4]),"=r"((r)[5]),"=r"((r)[6]),"=r"((r)[7]), \
          "=r"((r)[8]),"=r"((r)[9]),"=r"((r)[10]),"=r"((r)[11]),"=r"((r)[12]),"=r"((r)[13]),"=r"((r)[14]),"=r"((r)[15]), \
          "=r"((r)[16]),"=r"((r)[17]),"=r"((r)[18]),"=r"((r)[19]),"=r"((r)[20]),"=r"((r)[21]),"=r"((r)[22]),"=r"((r)[23]), \
          "=r"((r)[24]),"=r"((r)[25]),"=r"((r)[26]),"=r"((r)[27]),"=r"((r)[28]),"=r"((r)[29]),"=r"((r)[30]),"=r"((r)[31]) \
        : "r"(addr))
#endif

// ---------------- CSR build -------------------------------------------------
__global__ void k_zero_deg() {
    int i = blockIdx.x * blockDim.x + threadIdx.x;
    if (i < MTOT) g_deg[i] = 0;
}
__global__ void k_count(const int* __restrict__ dst) {
    int e = blockIdx.x * blockDim.x + threadIdx.x;
    if (e < NE) atomicAdd(&g_deg[dst[e]], 1);
}
__global__ void k_scan_dinv() {
    __shared__ int sh[1024];
    __shared__ int s_carry;
    int tid = threadIdx.x;
    if (tid == 0) s_carry = 0;
    __syncthreads();
    for (int base = 0; base < MTOT; base += 1024) {
        int i = base + tid;
        int v = (i < MTOT) ? g_deg[i] : 0;
        sh[tid] = v;
        __syncthreads();
        for (int ofs = 1; ofs < 1024; ofs <<= 1) {
            int t = (tid >= ofs) ? sh[tid - ofs] : 0;
            __syncthreads();
            sh[tid] += t;
            __syncthreads();
        }
        int incl = sh[tid];
        int carry = s_carry;
        if (i < MTOT) {
            int start = carry + incl - v;
            g_off[i] = start;
            g_cur[i] = start;
            g_dinv[i] = (v > 0) ? rsqrtf((float)v) : 0.0f;
        }
        __syncthreads();
        if (tid == 1023) s_carry = carry + incl;
        __syncthreads();
    }
    if (tid == 0) g_off[MTOT] = s_carry;
}
__global__ void k_scatter(const int* __restrict__ src, const int* __restrict__ dst) {
    int e = blockIdx.x * blockDim.x + threadIdx.x;
    if (e < NE) {
        int p = atomicAdd(&g_cur[dst[e]], 1);
        g_csrc[p] = src[e];
    }
}

// ---------------- converters ------------------------------------------------
__global__ void k_convW(const float* __restrict__ W, int K, int N,
                        __nv_bfloat16* __restrict__ oh, __nv_bfloat16* __restrict__ ol) {
    int idx = blockIdx.x * blockDim.x + threadIdx.x;
    if (idx >= K * N) return;
    int k = idx / N, n = idx % N;
    float v = W[idx];
    __nv_bfloat16 h = __float2bfloat16_rn(v);
    oh[(size_t)n * K + k] = h;
    ol[(size_t)n * K + k] = __float2bfloat16_rn(v - __bfloat162float(h));
}

__global__ void k_convX(const float* __restrict__ x,
                        __nv_bfloat16* __restrict__ oh, __nv_bfloat16* __restrict__ ol) {
    int idx = blockIdx.x * blockDim.x + threadIdx.x;
    if (idx >= MTOT * 32) return;
    int m = idx >> 5, c4 = (idx & 31) << 2;
    float4 v = *reinterpret_cast<const float4*>(x + (size_t)m * 128 + c4);
    uint2 hp, lp;
    hp.x = pk2(v.x, v.y); hp.y = pk2(v.z, v.w);
    lp.x = pk2(v.x - bhi(v.x), v.y - bhi(v.y));
    lp.y = pk2(v.z - bhi(v.z), v.w - bhi(v.w));
    *reinterpret_cast<uint2*>((char*)oh + ((size_t)m * 256 + c4) * 2) = hp;
    *reinterpret_cast<uint2*>((char*)ol + ((size_t)m * 256 + c4) * 2) = lp;
}

// ---------------- SpMM: x1 cols [F,2F) of A buffers (bf16 hi/lo) -------------
template <int CPL>
__global__ void k_spmm(__nv_bfloat16* __restrict__ Ahi, __nv_bfloat16* __restrict__ Alo,
                       int K, int F) {
    int node = blockIdx.x * 8 + (threadIdx.x >> 5);
    if (node >= MTOT) return;
    int lane = threadIdx.x & 31;
    int col = lane * CPL;
    float acc[CPL];
#pragma unroll
    for (int i = 0; i < CPL; i++) acc[i] = 0.f;
    float dv = g_dinv[node];
    int e0 = g_off[node], e1 = g_off[node + 1];
    const char* Ah = (const char*)Ahi;
    const char* Al = (const char*)Alo;
    for (int e = e0; e < e1; e++) {
        int j = g_csrc[e];
        float dj = g_dinv[j];
        size_t go = ((size_t)j * K + col) * 2;
        if constexpr (CPL == 8) {
            uint4 ph = *reinterpret_cast<const uint4*>(Ah + go);
            uint4 pl = *reinterpret_cast<const uint4*>(Al + go);
            uint32_t hw[4] = {ph.x, ph.y, ph.z, ph.w};
            uint32_t lw[4] = {pl.x, pl.y, pl.z, pl.w};
#pragma unroll
            for (int q = 0; q < 4; q++) {
                float a0 = __uint_as_float(hw[q] << 16) + __uint_as_float(lw[q] << 16);
                float a1 = __uint_as_float(hw[q] & 0xffff0000u) + __uint_as_float(lw[q] & 0xffff0000u);
                acc[2 * q]     += dj * a0;
                acc[2 * q + 1] += dj * a1;
            }
        } else {
            uint2 ph = *reinterpret_cast<const uint2*>(Ah + go);
            uint2 pl = *reinterpret_cast<const uint2*>(Al + go);
            uint32_t hw[2] = {ph.x, ph.y};
            uint32_t lw[2] = {pl.x, pl.y};
#pragma unroll
            for (int q = 0; q < 2; q++) {
                float a0 = __uint_as_float(hw[q] << 16) + __uint_as_float(lw[q] << 16);
                float a1 = __uint_as_float(hw[q] & 0xffff0000u) + __uint_as_float(lw[q] & 0xffff0000u);
                acc[2 * q]     += dj * a0;
                acc[2 * q + 1] += dj * a1;
            }
        }
    }
    float v[CPL];
#pragma unroll
    for (int i = 0; i < CPL; i++) v[i] = -dv * acc[i];
    size_t wo = ((size_t)node * K + F + col) * 2;
    if constexpr (CPL == 8) {
        uint4 hp, lp;
        hp.x = pk2(v[0], v[1]); hp.y = pk2(v[2], v[3]);
        hp.z = pk2(v[4], v[5]); hp.w = pk2(v[6], v[7]);
        lp.x = pk2(v[0] - bhi(v[0]), v[1] - bhi(v[1]));
        lp.y = pk2(v[2] - bhi(v[2]), v[3] - bhi(v[3]));
        lp.z = pk2(v[4] - bhi(v[4]), v[5] - bhi(v[5]));
        lp.w = pk2(v[6] - bhi(v[6]), v[7] - bhi(v[7]));
        *reinterpret_cast<uint4*>((char*)Ahi + wo) = hp;
        *reinterpret_cast<uint4*>((char*)Alo + wo) = lp;
    } else {
        uint2 hp, lp;
        hp.x = pk2(v[0], v[1]); hp.y = pk2(v[2], v[3]);
        lp.x = pk2(v[0] - bhi(v[0]), v[1] - bhi(v[1]));
        lp.y = pk2(v[2] - bhi(v[2]), v[3] - bhi(v[3]));
        *reinterpret_cast<uint2*>((char*)Ahi + wo) = hp;
        *reinterpret_cast<uint2*>((char*)Alo + wo) = lp;
    }
}

// ---------------- tcgen05 bf16x3 GEMM (arch-specific passes only) ------------
// Tile: M=128 x N=Nout, chunks of KC=64 (=128B SW128 rows), 2-stage pipeline.
// Stage layout (offsets): Ahi 0, Alo 16K, Bhi 32K, Blo 64K (96KB/stage).
__global__ void __launch_bounds__(256, 1) k_gemm_tc(
    const __nv_bfloat16* __restrict__ Ahi, const __nv_bfloat16* __restrict__ Alo, int K,
    const __nv_bfloat16* __restrict__ Bhi, const __nv_bfloat16* __restrict__ Blo,
    const float* __restrict__ bias, int Nout, uint32_t idesc, int act,
    __nv_bfloat16* __restrict__ oHi, __nv_bfloat16* __restrict__ oLo, int Kout,
    float* __restrict__ oF32)
{
#if TC_OK
    extern __shared__ char smraw[];
    __shared__ __align__(16) uint32_t ctrl[6];  // [0]=tmem ptr, +8/+16 = mbar x2
    int tid = threadIdx.x, wid = tid >> 5;
    uint32_t cu = smem_u32(ctrl);

    if (wid == 0) {
        asm volatile("tcgen05.alloc.cta_group::1.sync.aligned.shared::cta.b32 [%0], %1;"
                     :: "r"(cu), "r"(256u) : "memory");
        asm volatile("tcgen05.relinquish_alloc_permit.cta_group::1.sync.aligned;");
    }
    if (tid == 0) { mbar_init(cu + 8, 1); mbar_init(cu + 16, 1); }
    __syncthreads();
    uint32_t tmem;
    asm("ld.shared.b32 %0, [%1];" : "=r"(tmem) : "r"(cu));

    uint32_t raw = smem_u32(smraw);
    uint32_t sb = (raw + 1023) & ~1023u;
    char* sm = smraw + (sb - raw);

    int m0 = blockIdx.x * 128;
    const char* Ah = (const char*)Ahi;
    const char* Al = (const char*)Alo;
    const char* Bh = (const char*)Bhi;
    const char* Bl = (const char*)Blo;
    int NC = K >> 6;
    int nb8 = Nout << 3;

    for (int kc = 0; kc < NC; kc++) {
        int buf = kc & 1;
        char* st = sm + buf * 98304;
        uint32_t stu = sb + buf * 98304;
        if (kc >= 2) mbar_wait(cu + 8 + buf * 8, ((kc >> 1) - 1) & 1);

        // A tiles (128 rows x 64 bf16, hi+lo)
        for (int i = tid; i < 1024; i += 256) {
            int row = i >> 3, c = i & 7;
            int m = m0 + row;
            uint4 vh = make_uint4(0, 0, 0, 0), vl = vh;
            if (m < MTOT) {
                size_t go = ((size_t)m * K + (kc << 6) + (c << 3)) * 2;
                vh = *reinterpret_cast<const uint4*>(Ah + go);
                vl = *reinterpret_cast<const uint4*>(Al + go);
            }
            uint32_t bo = (row << 7) + (c << 4);
            uint32_t so = bo ^ ((bo >> 3) & 0x70);
            *reinterpret_cast<uint4*>(st + so) = vh;
            *reinterpret_cast<uint4*>(st + 16384 + so) = vl;
        }
        // B tiles (Nout rows x 64 bf16, hi+lo)  [W pre-transposed to (N,K)]
        for (int i = tid; i < nb8; i += 256) {
            int n = i >> 3, c = i & 7;
            size_t go = ((size_t)n * K + (kc << 6) + (c << 3)) * 2;
            uint4 vh = *reinterpret_cast<const uint4*>(Bh + go);
            uint4 vl = *reinterpret_cast<const uint4*>(Bl + go);
            uint32_t bo = (n << 7) + (c << 4);
            uint32_t so = bo ^ ((bo >> 3) & 0x70);
            *reinterpret_cast<uint4*>(st + 32768 + so) = vh;
            *reinterpret_cast<uint4*>(st + 65536 + so) = vl;
        }
        asm volatile("fence.proxy.async.shared::cta;" ::: "memory");
        __syncthreads();

        if (wid == 0 && elect1()) {
            uint64_t dAh = mk_desc(stu);
            uint64_t dAl = mk_desc(stu + 16384);
            uint64_t dBh = mk_desc(stu + 32768);
            uint64_t dBl = mk_desc(stu + 65536);
#pragma unroll
            for (int s = 0; s < 4; s++) {
                uint64_t o = (uint64_t)(s * 2);
                mma_ss_f16(tmem, dAh + o, dBh + o, idesc, (uint32_t)((kc | s) != 0));
                mma_ss_f16(tmem, dAh + o, dBl + o, idesc, 1u);
                mma_ss_f16(tmem, dAl + o, dBh + o, idesc, 1u);
            }
            asm volatile("tcgen05.commit.cta_group::1.mbarrier::arrive::one.shared::cluster.b64 [%0];"
                         :: "r"(cu + 8 + buf * 8) : "memory");
        }
    }

    mbar_wait(cu + 8 + ((NC - 1) & 1) * 8, ((NC - 1) >> 1) & 1);
    asm volatile("tcgen05.fence::after_thread_sync;" ::: "memory");

    // epilogue: 2 warpgroups split columns; warp%4 = TMEM subpartition (rows)
    int lane = tid & 31, sub = wid & 3, wg = wid >> 2;
    int m = m0 + sub * 32 + lane;
    int half = Nout >> 1;
    int colbase = wg * half;
    for (int cc = 0; cc < 4 && cc * 32 < half; cc++) {
        uint32_t r[32];
        LDTM32(r, tmem + colbase + cc * 32);
        asm volatile("tcgen05.wait::ld.sync.aligned;" ::: "memory");
        if (m < MTOT) {
            int nb = colbase + cc * 32;
            if (oF32) {
                float4* dp = reinterpret_cast<float4*>(oF32 + (size_t)m * Nout + nb);
#pragma unroll
                for (int q = 0; q < 8; q++) {
                    float4 v;
                    v.x = __uint_as_float(r[q * 4 + 0]) + bias[nb + q * 4 + 0];
                    v.y = __uint_as_float(r[q * 4 + 1]) + bias[nb + q * 4 + 1];
                    v.z = __uint_as_float(r[q * 4 + 2]) + bias[nb + q * 4 + 2];
                    v.w = __uint_as_float(r[q * 4 + 3]) + bias[nb + q * 4 + 3];
                    if (act) { v.x = tanha(v.x); v.y = tanha(v.y); v.z = tanha(v.z); v.w = tanha(v.w); }
                    dp[q] = v;
                }
            } else {
                uint32_t hp[16], lp[16];
#pragma unroll
                for (int q = 0; q < 16; q++) {
                    float v0 = __uint_as_float(r[2 * q])     + bias[nb + 2 * q];
                    float v1 = __uint_as_float(r[2 * q + 1]) + bias[nb + 2 * q + 1];
                    if (act) { v0 = tanha(v0); v1 = tanha(v1); }
                    float h0 = bhi(v0), h1 = bhi(v1);
                    hp[q] = pk2(v0, v1);
                    lp[q] = pk2(v0 - h0, v1 - h1);
                }
                uint4* dh = reinterpret_cast<uint4*>((char*)oHi + ((size_t)m * Kout + nb) * 2);
                uint4* dl = reinterpret_cast<uint4*>((char*)oLo + ((size_t)m * Kout + nb) * 2);
#pragma unroll
                for (int q = 0; q < 4; q++) {
                    dh[q] = make_uint4(hp[4 * q], hp[4 * q + 1], hp[4 * q + 2], hp[4 * q + 3]);
                    dl[q] = make_uint4(lp[4 * q], lp[4 * q + 1], lp[4 * q + 2], lp[4 * q + 3]);
                }
            }
        }
    }
    __syncthreads();
    if (wid == 0) {
        asm volatile("tcgen05.dealloc.cta_group::1.sync.aligned.b32 %0, %1;"
                     :: "r"(tmem), "r"(256u));
    }
#endif  // TC_OK
}

// ---------------- SIMT fallback GEMM (non-"a" passes only) -------------------
__global__ void __launch_bounds__(256) k_gemm_fb(
    const __nv_bfloat16* __restrict__ Ahi, const __nv_bfloat16* __restrict__ Alo, int K,
    const __nv_bfloat16* __restrict__ Bhi, const __nv_bfloat16* __restrict__ Blo,
    const float* __restrict__ bias, int Nout, uint32_t idesc, int act,
    __nv_bfloat16* __restrict__ oHi, __nv_bfloat16* __restrict__ oLo, int Kout,
    float* __restrict__ oF32)
{
#if !TC_OK
    __shared__ float As[16][132];
    __shared__ float Bs[16][128];
    int tid = threadIdx.x;
    int tx = tid & 15, ty = tid >> 4;
    int m0 = blockIdx.x * 128;

    for (int n0 = 0; n0 < Nout; n0 += 128) {
        float acc[8][8];
#pragma unroll
        for (int i = 0; i < 8; i++)
#pragma unroll
            for (int j = 0; j < 8; j++) acc[i][j] = 0.f;

        for (int k0 = 0; k0 < K; k0 += 16) {
            for (int i = tid; i < 2048; i += 256) {
                int r = i >> 4, k = i & 15;
                int m = m0 + r;
                float v = 0.f;
                if (m < MTOT) {
                    size_t o = (size_t)m * K + k0 + k;
                    v = __bfloat162float(Ahi[o]) + __bfloat162float(Alo[o]);
                }
                As[k][r] = v;
            }
            for (int i = tid; i < 2048; i += 256) {
                int r = i >> 4, k = i & 15;
                size_t o = (size_t)(n0 + r) * K + k0 + k;
                Bs[k][r] = __bfloat162float(Bhi[o]) + __bfloat162float(Blo[o]);
            }
            __syncthreads();
#pragma unroll
            for (int k = 0; k < 16; k++) {
                float a[8], b[8];
#pragma unroll
                for (int i = 0; i < 8; i++) a[i] = As[k][ty * 8 + i];
#pragma unroll
                for (int j = 0; j < 8; j++) b[j] = Bs[k][tx * 8 + j];
#pragma unroll
                for (int i = 0; i < 8; i++)
#pragma unroll
                    for (int j = 0; j < 8; j++) acc[i][j] += a[i] * b[j];
            }
            __syncthreads();
        }

#pragma unroll
        for (int i = 0; i < 8; i++) {
            int m = m0 + ty * 8 + i;
            if (m >= MTOT) continue;
#pragma unroll
            for (int j = 0; j < 8; j++) {
                int n = n0 + tx * 8 + j;
                float v = acc[i][j] + bias[n];
                if (act) v = tanhf(v);
                if (oF32) {
                    oF32[(size_t)m * Nout + n] = v;
                } else {
                    __nv_bfloat16 h = __float2bfloat16_rn(v);
                    oHi[(size_t)m * Kout + n] = h;
                    oLo[(size_t)m * Kout + n] = __float2bfloat16_rn(v - __bfloat162float(h));
                }
            }
        }
        __syncthreads();
    }
#endif  // !TC_OK
}

// ---------------- launch -----------------------------------------------------
static inline uint32_t mk_idesc(int N) {
    return (1u << 4) | (1u << 7) | (1u << 10) | ((uint32_t)(N / 8) << 17) | (8u << 24);
}

extern "C" void kernel_launch(void* const* d_in, const int* in_sizes, int n_in,
                              void* d_out, int out_size) {
    const float* x   = (const float*)d_in[0];
    const int*   src = (const int*)d_in[1];
    const int*   dst = (const int*)d_in[2];
    const float* W1  = (const float*)d_in[3];
    const float* b1  = (const float*)d_in[4];
    const float* W2  = (const float*)d_in[5];
    const float* b2  = (const float*)d_in[6];
    const float* W3  = (const float*)d_in[7];
    const float* b3  = (const float*)d_in[8];
    float* out = (float*)d_out;

    void *p;
    cudaGetSymbolAddress(&p, g_AhiA); __nv_bfloat16* AhiA = (__nv_bfloat16*)p;
    cudaGetSymbolAddress(&p, g_AloA); __nv_bfloat16* AloA = (__nv_bfloat16*)p;
    cudaGetSymbolAddress(&p, g_AhiB); __nv_bfloat16* AhiB = (__nv_bfloat16*)p;
    cudaGetSymbolAddress(&p, g_AloB); __nv_bfloat16* AloB = (__nv_bfloat16*)p;
    cudaGetSymbolAddress(&p, g_Wthi); __nv_bfloat16* Wth = (__nv_bfloat16*)p;
    cudaGetSymbolAddress(&p, g_Wtlo); __nv_bfloat16* Wtl = (__nv_bfloat16*)p;

    cudaFuncSetAttribute(k_gemm_tc, cudaFuncAttributeMaxDynamicSharedMemorySize, 197632);

    // CSR build
    k_zero_deg<<<(MTOT + 255) / 256, 256>>>();
    k_count<<<(NE + 255) / 256, 256>>>(dst);
    k_scan_dinv<<<1, 1024>>>();
    k_scatter<<<(NE + 255) / 256, 256>>>(src, dst);

    // weight + input conversion
    k_convW<<<(256 * 256 + 255) / 256, 256>>>(W1, 256, 256, Wth, Wtl);
    k_convW<<<(512 * 256 + 255) / 256, 256>>>(W2, 512, 256, Wth + 65536, Wtl + 65536);
    k_convW<<<(512 * 128 + 255) / 256, 256>>>(W3, 512, 128, Wth + 196608, Wtl + 196608);
    k_convX<<<(MTOT * 32 + 255) / 256, 256>>>(x, AhiA, AloA);

    uint32_t id256 = mk_idesc(256), id128 = mk_idesc(128);
    int gg = (MTOT + 127) / 128;  // 391
    int gs = (MTOT + 7) / 8;      // 6250
    size_t shm = 197632;

    // Exactly one of k_gemm_tc / k_gemm_fb has a body in the loaded image;
    // launch both so behavior is correct regardless of which pass runs.
    auto layer = [&](const __nv_bfloat16* ah, const __nv_bfloat16* al, int K,
                     const __nv_bfloat16* bh, const __nv_bfloat16* bl,
                     const float* bias, int Nout, uint32_t idesc, int act,
                     __nv_bfloat16* ohh, __nv_bfloat16* oll, int Kout, float* of) {
        k_gemm_tc<<<gg, 256, shm>>>(ah, al, K, bh, bl, bias, Nout, idesc, act, ohh, oll, Kout, of);
        k_gemm_fb<<<gg, 256>>>(ah, al, K, bh, bl, bias, Nout, idesc, act, ohh, oll, Kout, of);
    };

    // L1: F=128, K=256
    k_spmm<4><<<gs, 256>>>(AhiA, AloA, 256, 128);
    layer(AhiA, AloA, 256, Wth, Wtl, b1, 256, id256, 1, AhiB, AloB, 512, nullptr);
    // L2
    k_spmm<8><<<gs, 256>>>(AhiB, AloB, 512, 256);
    layer(AhiB, AloB, 512, Wth + 65536, Wtl + 65536, b2, 256, id256, 1, AhiA, AloA, 512, nullptr);
    // L3
    k_spmm<8><<<gs, 256>>>(AhiA, AloA, 512, 256);
    layer(AhiA, AloA, 512, Wth + 65536, Wtl + 65536, b2, 256, id256, 1, AhiB, AloB, 512, nullptr);
    // L4
    k_spmm<8><<<gs, 256>>>(AhiB, AloB, 512, 256);
    layer(AhiB, AloB, 512, Wth + 65536, Wtl + 65536, b2, 256, id256, 1, AhiA, AloA, 512, nullptr);
    // L5: out fp32, no act
    k_spmm<8><<<gs, 256>>>(AhiA, AloA, 512, 256);
    layer(AhiA, AloA, 512, Wth + 196608, Wtl + 196608, b3, 128, id128, 0, nullptr, nullptr, 0, out);
}

// round 4
// speedup vs baseline: 2.1337x; 1.1203x over previous
#include <cuda_runtime.h>
#include <cuda_bf16.h>
#include <cuda_fp16.h>
#include <stdint.h>
#include <math.h>

#define MTOT 50000
#define NE   800000

// tcgen05 is an arch-SPECIFIC ("a") feature. Guard it so the plain compute_103
// PTX pass compiles; that pass gets the SIMT fallback body instead.
#if defined(__CUDA_ARCH_FEAT_SM103_ALL) || defined(__CUDA_ARCH_FEAT_SM100_ALL) || \
    defined(__CUDA_ARCH_FEAT_SM101_ALL) || defined(__CUDA_ARCH_FEAT_SM110_ALL)
#define TC_OK 1
#else
#define TC_OK 0
#endif

// ---------------- device scratch (no cudaMalloc) ----------------------------
__device__ __align__(16) __nv_bfloat16 g_Ahi[(size_t)MTOT * 256];
__device__ __align__(16) __nv_bfloat16 g_Alo[(size_t)MTOT * 256];
__device__ __align__(16) float  g_yh[(size_t)MTOT * 256];
__device__ __align__(16) __half g_yx[(size_t)MTOT * 256];
__device__ __align__(16) __nv_bfloat16 g_Wthi[262144];
__device__ __align__(16) __nv_bfloat16 g_Wtlo[262144];
__device__ float g_dinv[MTOT];
__device__ int   g_deg[MTOT];
__device__ int   g_off[MTOT + 1];
__device__ int   g_cur[MTOT];
__device__ int   g_csrc[NE];

// ---------------- small helpers ---------------------------------------------
__device__ __forceinline__ uint32_t smem_u32(const void* p) {
    uint32_t a;
    asm("{ .reg .u64 t; cvta.to.shared.u64 t, %1; cvt.u32.u64 %0, t; }" : "=r"(a) : "l"(p));
    return a;
}
__device__ __forceinline__ bool elect1() {
    uint32_t p;
    asm volatile("{\n\t.reg .pred p;\n\telect.sync _|p, 0xFFFFFFFF;\n\tselp.b32 %0,1,0,p;\n\t}" : "=r"(p));
    return p != 0;
}
__device__ __forceinline__ void mbar_init(uint32_t mbar, uint32_t cnt) {
    asm volatile("mbarrier.init.shared.b64 [%0], %1;" :: "r"(mbar), "r"(cnt) : "memory");
}
__device__ __forceinline__ void mbar_wait(uint32_t mbar, uint32_t parity) {
    uint32_t done;
    asm volatile("{\n\t.reg .pred p;\n\tmbarrier.try_wait.parity.acquire.cta.shared::cta.b64 p, [%1], %2;\n\tselp.b32 %0,1,0,p;\n\t}"
                 : "=r"(done) : "r"(mbar), "r"(parity) : "memory");
    if (!done) {
        asm volatile("{\n\t.reg .pred P1;\nWL_%=:\n\tmbarrier.try_wait.parity.acquire.cta.shared::cta.b64 P1, [%0], %1, 0x989680;\n\t@P1 bra.uni WD_%=;\n\tbra.uni WL_%=;\nWD_%=:\n\t}"
                     :: "r"(mbar), "r"(parity) : "memory");
    }
}
__device__ __forceinline__ float tanha(float x) {
    float y; asm("tanh.approx.f32 %0, %1;" : "=f"(y) : "f"(x)); return y;
}
__device__ __forceinline__ float bhi(float v) {
    return __bfloat162float(__float2bfloat16_rn(v));
}
__device__ __forceinline__ uint32_t pk2(float a, float b) {
    uint16_t ha = __bfloat16_as_ushort(__float2bfloat16_rn(a));
    uint16_t hb = __bfloat16_as_ushort(__float2bfloat16_rn(b));
    return (uint32_t)ha | ((uint32_t)hb << 16);
}
__device__ __forceinline__ uint32_t pkh2(float a, float b) {
    __half2 h = __floats2half2_rn(a, b);
    return *reinterpret_cast<uint32_t*>(&h);
}

#if TC_OK
__device__ __forceinline__ uint64_t mk_desc(uint32_t addr) {
    // SW128, version=1(Blackwell), SBO=64, LBO=1, start=addr>>4
    return 0x4000404000010000ULL | ((uint64_t)(addr >> 4) & 0x3FFF);
}
__device__ __forceinline__ void mma_ss_f16(uint32_t d, uint64_t ad, uint64_t bd,
                                           uint32_t idesc, uint32_t en) {
    asm volatile("{\n\t.reg .pred p;\n\tsetp.ne.u32 p, %4, 0;\n\t"
                 "tcgen05.mma.cta_group::1.kind::f16 [%0], %1, %2, %3, {%5,%5,%5,%5}, p;\n\t}"
                 :: "r"(d), "l"(ad), "l"(bd), "r"(idesc), "r"(en), "r"(0u) : "memory");
}
#define LDTM32(r, addr) \
    asm volatile("tcgen05.ld.sync.aligned.32x32b.x32.b32 " \
        "{%0,%1,%2,%3,%4,%5,%6,%7,%8,%9,%10,%11,%12,%13,%14,%15," \
        "%16,%17,%18,%19,%20,%21,%22,%23,%24,%25,%26,%27,%28,%29,%30,%31}, [%32];" \
        : "=r"((r)[0]),"=r"((r)[1]),"=r"((r)[2]),"=r"((r)[3]),"=r"((r)[4]),"=r"((r)[5]),"=r"((r)[6]),"=r"((r)[7]), \
          "=r"((r)[8]),"=r"((r)[9]),"=r"((r)[10]),"=r"((r)[11]),"=r"((r)[12]),"=r"((r)[13]),"=r"((r)[14]),"=r"((r)[15]), \
          "=r"((r)[16]),"=r"((r)[17]),"=r"((r)[18]),"=r"((r)[19]),"=r"((r)[20]),"=r"((r)[21]),"=r"((r)[22]),"=r"((r)[23]), \
          "=r"((r)[24]),"=r"((r)[25]),"=r"((r)[26]),"=r"((r)[27]),"=r"((r)[28]),"=r"((r)[29]),"=r"((r)[30]),"=r"((r)[31]) \
        : "r"(addr))
#endif

// ---------------- CSR build -------------------------------------------------
__global__ void k_zero_deg() {
    int i = blockIdx.x * blockDim.x + threadIdx.x;
    if (i < MTOT) g_deg[i] = 0;
}
__global__ void k_count(const int* __restrict__ dst) {
    int e = blockIdx.x * blockDim.x + threadIdx.x;
    if (e < NE) atomicAdd(&g_deg[dst[e]], 1);
}
__global__ void k_scan_dinv() {
    __shared__ int sh[1024];
    __shared__ int s_carry;
    int tid = threadIdx.x;
    if (tid == 0) s_carry = 0;
    __syncthreads();
    for (int base = 0; base < MTOT; base += 1024) {
        int i = base + tid;
        int v = (i < MTOT) ? g_deg[i] : 0;
        sh[tid] = v;
        __syncthreads();
        for (int ofs = 1; ofs < 1024; ofs <<= 1) {
            int t = (tid >= ofs) ? sh[tid - ofs] : 0;
            __syncthreads();
            sh[tid] += t;
            __syncthreads();
        }
        int incl = sh[tid];
        int carry = s_carry;
        if (i < MTOT) {
            int start = carry + incl - v;
            g_off[i] = start;
            g_cur[i] = start;
            g_dinv[i] = (v > 0) ? rsqrtf((float)v) : 0.0f;
        }
        __syncthreads();
        if (tid == 1023) s_carry = carry + incl;
        __syncthreads();
    }
    if (tid == 0) g_off[MTOT] = s_carry;
}
__global__ void k_scatter(const int* __restrict__ src, const int* __restrict__ dst) {
    int e = blockIdx.x * blockDim.x + threadIdx.x;
    if (e < NE) {
        int p = atomicAdd(&g_cur[dst[e]], 1);
        g_csrc[p] = src[e];
    }
}

// ---------------- converters ------------------------------------------------
// W (2F, N) row-major -> two transposed halves (N, F) each, hi/lo bf16.
// half0 = rows [0,F) (Wh), half1 = rows [F,2F) (Wx). half1 stored at +N*F.
__global__ void k_convW2(const float* __restrict__ W, int F, int N,
                         __nv_bfloat16* __restrict__ oh, __nv_bfloat16* __restrict__ ol) {
    int idx = blockIdx.x * blockDim.x + threadIdx.x;
    if (idx >= 2 * F * N) return;
    int k2 = idx / N, n = idx % N;
    int half = (k2 >= F);
    int k = k2 - half * F;
    float v = W[(size_t)k2 * N + n];
    __nv_bfloat16 h = __float2bfloat16_rn(v);
    size_t o = (size_t)half * N * F + (size_t)n * F + k;
    oh[o] = h;
    ol[o] = __float2bfloat16_rn(v - __bfloat162float(h));
}

__global__ void k_convX(const float* __restrict__ x,
                        __nv_bfloat16* __restrict__ oh, __nv_bfloat16* __restrict__ ol) {
    int idx = blockIdx.x * blockDim.x + threadIdx.x;
    if (idx >= MTOT * 32) return;
    int m = idx >> 5, c4 = (idx & 31) << 2;
    float4 v = *reinterpret_cast<const float4*>(x + (size_t)m * 128 + c4);
    uint2 hp, lp;
    hp.x = pk2(v.x, v.y); hp.y = pk2(v.z, v.w);
    lp.x = pk2(v.x - bhi(v.x), v.y - bhi(v.y));
    lp.y = pk2(v.z - bhi(v.z), v.w - bhi(v.w));
    *reinterpret_cast<uint2*>((char*)oh + ((size_t)m * 128 + c4) * 2) = hp;
    *reinterpret_cast<uint2*>((char*)ol + ((size_t)m * 128 + c4) * 2) = lp;
}

// ---------------- aggregation + activation ----------------------------------
// h' = tanh(yh - dinv_n * sum_j yx[j])   (yx already has dinv_j folded in)
// ACT=1: write bf16 hi/lo activation. ACT=0: write fp32 (final output).
template <int CPL, int ACT>
__global__ void k_aggact(const float* __restrict__ yh, const __half* __restrict__ yx,
                         int Nout, __nv_bfloat16* __restrict__ oh,
                         __nv_bfloat16* __restrict__ ol, float* __restrict__ of32) {
    int node = blockIdx.x * 8 + (threadIdx.x >> 5);
    if (node >= MTOT) return;
    int lane = threadIdx.x & 31;
    int col = lane * CPL;
    float acc[CPL];
#pragma unroll
    for (int i = 0; i < CPL; i++) acc[i] = 0.f;
    int e0 = g_off[node], e1 = g_off[node + 1];
    const char* yxb = (const char*)yx;
    int e = e0;
    for (; e + 2 <= e1; e += 2) {
        int j0 = g_csrc[e], j1 = g_csrc[e + 1];
        if constexpr (CPL == 8) {
            uint4 p0 = *reinterpret_cast<const uint4*>(yxb + ((size_t)j0 * Nout + col) * 2);
            uint4 p1 = *reinterpret_cast<const uint4*>(yxb + ((size_t)j1 * Nout + col) * 2);
            uint32_t w0[4] = {p0.x, p0.y, p0.z, p0.w};
            uint32_t w1[4] = {p1.x, p1.y, p1.z, p1.w};
#pragma unroll
            for (int q = 0; q < 4; q++) {
                float2 f0 = __half22float2(*reinterpret_cast<__half2*>(&w0[q]));
                float2 f1 = __half22float2(*reinterpret_cast<__half2*>(&w1[q]));
                acc[2 * q]     += f0.x + f1.x;
                acc[2 * q + 1] += f0.y + f1.y;
            }
        } else {
            uint2 p0 = *reinterpret_cast<const uint2*>(yxb + ((size_t)j0 * Nout + col) * 2);
            uint2 p1 = *reinterpret_cast<const uint2*>(yxb + ((size_t)j1 * Nout + col) * 2);
            uint32_t w0[2] = {p0.x, p0.y};
            uint32_t w1[2] = {p1.x, p1.y};
#pragma unroll
            for (int q = 0; q < 2; q++) {
                float2 f0 = __half22float2(*reinterpret_cast<__half2*>(&w0[q]));
                float2 f1 = __half22float2(*reinterpret_cast<__half2*>(&w1[q]));
                acc[2 * q]     += f0.x + f1.x;
                acc[2 * q + 1] += f0.y + f1.y;
            }
        }
    }
    if (e < e1) {
        int j0 = g_csrc[e];
        if constexpr (CPL == 8) {
            uint4 p0 = *reinterpret_cast<const uint4*>(yxb + ((size_t)j0 * Nout + col) * 2);
            uint32_t w0[4] = {p0.x, p0.y, p0.z, p0.w};
#pragma unroll
            for (int q = 0; q < 4; q++) {
                float2 f0 = __half22float2(*reinterpret_cast<__half2*>(&w0[q]));
                acc[2 * q] += f0.x; acc[2 * q + 1] += f0.y;
            }
        } else {
            uint2 p0 = *reinterpret_cast<const uint2*>(yxb + ((size_t)j0 * Nout + col) * 2);
            uint32_t w0[2] = {p0.x, p0.y};
#pragma unroll
            for (int q = 0; q < 2; q++) {
                float2 f0 = __half22float2(*reinterpret_cast<__half2*>(&w0[q]));
                acc[2 * q] += f0.x; acc[2 * q + 1] += f0.y;
            }
        }
    }
    float dv = g_dinv[node];
    float v[CPL];
#pragma unroll
    for (int i = 0; i < CPL; i += 4) {
        float4 y = *reinterpret_cast<const float4*>(yh + (size_t)node * Nout + col + i);
        v[i + 0] = y.x - dv * acc[i + 0];
        v[i + 1] = y.y - dv * acc[i + 1];
        v[i + 2] = y.z - dv * acc[i + 2];
        v[i + 3] = y.w - dv * acc[i + 3];
    }
    if constexpr (ACT) {
#pragma unroll
        for (int i = 0; i < CPL; i++) v[i] = tanha(v[i]);
        size_t wo = ((size_t)node * Nout + col) * 2;
        if constexpr (CPL == 8) {
            uint4 hp, lp;
            hp.x = pk2(v[0], v[1]); hp.y = pk2(v[2], v[3]);
            hp.z = pk2(v[4], v[5]); hp.w = pk2(v[6], v[7]);
            lp.x = pk2(v[0] - bhi(v[0]), v[1] - bhi(v[1]));
            lp.y = pk2(v[2] - bhi(v[2]), v[3] - bhi(v[3]));
            lp.z = pk2(v[4] - bhi(v[4]), v[5] - bhi(v[5]));
            lp.w = pk2(v[6] - bhi(v[6]), v[7] - bhi(v[7]));
            *reinterpret_cast<uint4*>((char*)oh + wo) = hp;
            *reinterpret_cast<uint4*>((char*)ol + wo) = lp;
        } else {
            uint2 hp, lp;
            hp.x = pk2(v[0], v[1]); hp.y = pk2(v[2], v[3]);
            lp.x = pk2(v[0] - bhi(v[0]), v[1] - bhi(v[1]));
            lp.y = pk2(v[2] - bhi(v[2]), v[3] - bhi(v[3]));
            *reinterpret_cast<uint2*>((char*)oh + wo) = hp;
            *reinterpret_cast<uint2*>((char*)ol + wo) = lp;
        }
    } else {
#pragma unroll
        for (int i = 0; i < CPL; i += 4) {
            float4 o = make_float4(v[i], v[i + 1], v[i + 2], v[i + 3]);
            *reinterpret_cast<float4*>(of32 + (size_t)node * Nout + col + i) = o;
        }
    }
}

// ---------------- tcgen05 bf16x3 GEMM ---------------------------------------
// grid (391, 2). blockIdx.y = 0: yh = h@Wh + b (fp32 out)
//                blockIdx.y = 1: yx = dinv_m * (h@Wx) (fp16 out)
// B halves contiguous: Bhi + half*Nout*K.
__global__ void __launch_bounds__(256, 1) k_gemm_tc(
    const __nv_bfloat16* __restrict__ Ahi, const __nv_bfloat16* __restrict__ Alo, int K,
    const __nv_bfloat16* __restrict__ Bhi, const __nv_bfloat16* __restrict__ Blo,
    const float* __restrict__ bias, int Nout, uint32_t idesc,
    float* __restrict__ yh, __half* __restrict__ yx)
{
#if TC_OK
    extern __shared__ char smraw[];
    __shared__ __align__(16) uint32_t ctrl[6];  // [0]=tmem ptr, +8/+16 = mbar x2
    int tid = threadIdx.x, wid = tid >> 5;
    uint32_t cu = smem_u32(ctrl);

    if (wid == 0) {
        asm volatile("tcgen05.alloc.cta_group::1.sync.aligned.shared::cta.b32 [%0], %1;"
                     :: "r"(cu), "r"(256u) : "memory");
        asm volatile("tcgen05.relinquish_alloc_permit.cta_group::1.sync.aligned;");
    }
    if (tid == 0) { mbar_init(cu + 8, 1); mbar_init(cu + 16, 1); }
    __syncthreads();
    uint32_t tmem;
    asm("ld.shared.b32 %0, [%1];" : "=r"(tmem) : "r"(cu));

    uint32_t raw = smem_u32(smraw);
    uint32_t sb = (raw + 1023) & ~1023u;
    char* sm = smraw + (sb - raw);

    int m0 = blockIdx.x * 128;
    size_t hofs = (size_t)blockIdx.y * Nout * K;
    const char* Ah = (const char*)Ahi;
    const char* Al = (const char*)Alo;
    const char* Bh = (const char*)(Bhi + hofs);
    const char* Bl = (const char*)(Blo + hofs);
    int NC = K >> 6;
    int nb8 = Nout << 3;

    for (int kc = 0; kc < NC; kc++) {
        int buf = kc & 1;
        char* st = sm + buf * 98304;
        uint32_t stu = sb + buf * 98304;
        if (kc >= 2) mbar_wait(cu + 8 + buf * 8, ((kc >> 1) - 1) & 1);

        // A tiles (128 rows x 64 bf16, hi+lo)
        for (int i = tid; i < 1024; i += 256) {
            int row = i >> 3, c = i & 7;
            int m = m0 + row;
            uint4 vh = make_uint4(0, 0, 0, 0), vl = vh;
            if (m < MTOT) {
                size_t go = ((size_t)m * K + (kc << 6) + (c << 3)) * 2;
                vh = *reinterpret_cast<const uint4*>(Ah + go);
                vl = *reinterpret_cast<const uint4*>(Al + go);
            }
            uint32_t bo = (row << 7) + (c << 4);
            uint32_t so = bo ^ ((bo >> 3) & 0x70);
            *reinterpret_cast<uint4*>(st + so) = vh;
            *reinterpret_cast<uint4*>(st + 16384 + so) = vl;
        }
        // B tiles (Nout rows x 64 bf16, hi+lo)
        for (int i = tid; i < nb8; i += 256) {
            int n = i >> 3, c = i & 7;
            size_t go = ((size_t)n * K + (kc << 6) + (c << 3)) * 2;
            uint4 vh = *reinterpret_cast<const uint4*>(Bh + go);
            uint4 vl = *reinterpret_cast<const uint4*>(Bl + go);
            uint32_t bo = (n << 7) + (c << 4);
            uint32_t so = bo ^ ((bo >> 3) & 0x70);
            *reinterpret_cast<uint4*>(st + 32768 + so) = vh;
            *reinterpret_cast<uint4*>(st + 65536 + so) = vl;
        }
        asm volatile("fence.proxy.async.shared::cta;" ::: "memory");
        __syncthreads();

        if (wid == 0 && elect1()) {
            uint64_t dAh = mk_desc(stu);
            uint64_t dAl = mk_desc(stu + 16384);
            uint64_t dBh = mk_desc(stu + 32768);
            uint64_t dBl = mk_desc(stu + 65536);
#pragma unroll
            for (int s = 0; s < 4; s++) {
                uint64_t o = (uint64_t)(s * 2);
                mma_ss_f16(tmem, dAh + o, dBh + o, idesc, (uint32_t)((kc | s) != 0));
                mma_ss_f16(tmem, dAh + o, dBl + o, idesc, 1u);
                mma_ss_f16(tmem, dAl + o, dBh + o, idesc, 1u);
            }
            asm volatile("tcgen05.commit.cta_group::1.mbarrier::arrive::one.shared::cluster.b64 [%0];"
                         :: "r"(cu + 8 + buf * 8) : "memory");
        }
    }

    mbar_wait(cu + 8 + ((NC - 1) & 1) * 8, ((NC - 1) >> 1) & 1);
    asm volatile("tcgen05.fence::after_thread_sync;" ::: "memory");

    // epilogue: 2 warpgroups split columns; warp%4 = TMEM subpartition (rows)
    int lane = tid & 31, sub = wid & 3, wg = wid >> 2;
    int m = m0 + sub * 32 + lane;
    int halfc = Nout >> 1;
    int colbase = wg * halfc;
    for (int cc = 0; cc < 4 && cc * 32 < halfc; cc++) {
        uint32_t r[32];
        LDTM32(r, tmem + colbase + cc * 32);
        asm volatile("tcgen05.wait::ld.sync.aligned;" ::: "memory");
        if (m < MTOT) {
            int nb = colbase + cc * 32;
            if (blockIdx.y == 0) {
                float4* dp = reinterpret_cast<float4*>(yh + (size_t)m * Nout + nb);
#pragma unroll
                for (int q = 0; q < 8; q++) {
                    float4 v;
                    v.x = __uint_as_float(r[q * 4 + 0]) + bias[nb + q * 4 + 0];
                    v.y = __uint_as_float(r[q * 4 + 1]) + bias[nb + q * 4 + 1];
                    v.z = __uint_as_float(r[q * 4 + 2]) + bias[nb + q * 4 + 2];
                    v.w = __uint_as_float(r[q * 4 + 3]) + bias[nb + q * 4 + 3];
                    dp[q] = v;
                }
            } else {
                float dv = g_dinv[m];
                uint32_t hp[16];
#pragma unroll
                for (int q = 0; q < 16; q++) {
                    hp[q] = pkh2(dv * __uint_as_float(r[2 * q]),
                                 dv * __uint_as_float(r[2 * q + 1]));
                }
                uint4* dp = reinterpret_cast<uint4*>((char*)yx + ((size_t)m * Nout + nb) * 2);
#pragma unroll
                for (int q = 0; q < 4; q++)
                    dp[q] = make_uint4(hp[4 * q], hp[4 * q + 1], hp[4 * q + 2], hp[4 * q + 3]);
            }
        }
    }
    __syncthreads();
    if (wid == 0) {
        asm volatile("tcgen05.dealloc.cta_group::1.sync.aligned.b32 %0, %1;"
                     :: "r"(tmem), "r"(256u));
    }
#endif  // TC_OK
}

// ---------------- SIMT fallback GEMM (non-"a" passes only) -------------------
__global__ void __launch_bounds__(256) k_gemm_fb(
    const __nv_bfloat16* __restrict__ Ahi, const __nv_bfloat16* __restrict__ Alo, int K,
    const __nv_bfloat16* __restrict__ Bhi, const __nv_bfloat16* __restrict__ Blo,
    const float* __restrict__ bias, int Nout, uint32_t idesc,
    float* __restrict__ yh, __half* __restrict__ yx)
{
#if !TC_OK
    __shared__ float As[16][132];
    __shared__ float Bs[16][128];
    int tid = threadIdx.x;
    int tx = tid & 15, ty = tid >> 4;
    int m0 = blockIdx.x * 128;
    size_t hofs = (size_t)blockIdx.y * Nout * K;
    const __nv_bfloat16* Bh = Bhi + hofs;
    const __nv_bfloat16* Bl = Blo + hofs;

    for (int n0 = 0; n0 < Nout; n0 += 128) {
        float acc[8][8];
#pragma unroll
        for (int i = 0; i < 8; i++)
#pragma unroll
            for (int j = 0; j < 8; j++) acc[i][j] = 0.f;

        for (int k0 = 0; k0 < K; k0 += 16) {
            for (int i = tid; i < 2048; i += 256) {
                int r = i >> 4, k = i & 15;
                int m = m0 + r;
                float v = 0.f;
                if (m < MTOT) {
                    size_t o = (size_t)m * K + k0 + k;
                    v = __bfloat162float(Ahi[o]) + __bfloat162float(Alo[o]);
                }
                As[k][r] = v;
            }
            for (int i = tid; i < 2048; i += 256) {
                int r = i >> 4, k = i & 15;
                size_t o = (size_t)(n0 + r) * K + k0 + k;
                Bs[k][r] = __bfloat162float(Bh[o]) + __bfloat162float(Bl[o]);
            }
            __syncthreads();
#pragma unroll
            for (int k = 0; k < 16; k++) {
                float a[8], b[8];
#pragma unroll
                for (int i = 0; i < 8; i++) a[i] = As[k][ty * 8 + i];
#pragma unroll
                for (int j = 0; j < 8; j++) b[j] = Bs[k][tx * 8 + j];
#pragma unroll
                for (int i = 0; i < 8; i++)
#pragma unroll
                    for (int j = 0; j < 8; j++) acc[i][j] += a[i] * b[j];
            }
            __syncthreads();
        }

#pragma unroll
        for (int i = 0; i < 8; i++) {
            int m = m0 + ty * 8 + i;
            if (m >= MTOT) continue;
            float dv = g_dinv[m];
#pragma unroll
            for (int j = 0; j < 8; j++) {
                int n = n0 + tx * 8 + j;
                if (blockIdx.y == 0) yh[(size_t)m * Nout + n] = acc[i][j] + bias[n];
                else                 yx[(size_t)m * Nout + n] = __float2half_rn(dv * acc[i][j]);
            }
        }
        __syncthreads();
    }
#endif  // !TC_OK
}

// ---------------- launch -----------------------------------------------------
static inline uint32_t mk_idesc(int N) {
    return (1u << 4) | (1u << 7) | (1u << 10) | ((uint32_t)(N / 8) << 17) | (8u << 24);
}

extern "C" void kernel_launch(void* const* d_in, const int* in_sizes, int n_in,
                              void* d_out, int out_size) {
    const float* x   = (const float*)d_in[0];
    const int*   src = (const int*)d_in[1];
    const int*   dst = (const int*)d_in[2];
    const float* W1  = (const float*)d_in[3];
    const float* b1  = (const float*)d_in[4];
    const float* W2  = (const float*)d_in[5];
    const float* b2  = (const float*)d_in[6];
    const float* W3  = (const float*)d_in[7];
    const float* b3  = (const float*)d_in[8];
    float* out = (float*)d_out;

    void* p;
    cudaGetSymbolAddress(&p, g_Ahi);  __nv_bfloat16* Ahi = (__nv_bfloat16*)p;
    cudaGetSymbolAddress(&p, g_Alo);  __nv_bfloat16* Alo = (__nv_bfloat16*)p;
    cudaGetSymbolAddress(&p, g_yh);   float*  yh = (float*)p;
    cudaGetSymbolAddress(&p, g_yx);   __half* yx = (__half*)p;
    cudaGetSymbolAddress(&p, g_Wthi); __nv_bfloat16* Wth = (__nv_bfloat16*)p;
    cudaGetSymbolAddress(&p, g_Wtlo); __nv_bfloat16* Wtl = (__nv_bfloat16*)p;

    cudaFuncSetAttribute(k_gemm_tc, cudaFuncAttributeMaxDynamicSharedMemorySize, 197632);

    // CSR build
    k_zero_deg<<<(MTOT + 255) / 256, 256>>>();
    k_count<<<(NE + 255) / 256, 256>>>(dst);
    k_scan_dinv<<<1, 1024>>>();
    k_scatter<<<(NE + 255) / 256, 256>>>(src, dst);

    // weight + input conversion
    // layout: W1 halves @0/@32768; W2 halves @65536/@131072; W3 halves @196608/@229376
    k_convW2<<<(256 * 256 + 255) / 256, 256>>>(W1, 128, 256, Wth, Wtl);
    k_convW2<<<(512 * 256 + 255) / 256, 256>>>(W2, 256, 256, Wth + 65536, Wtl + 65536);
    k_convW2<<<(512 * 128 + 255) / 256, 256>>>(W3, 256, 128, Wth + 196608, Wtl + 196608);
    k_convX<<<(MTOT * 32 + 255) / 256, 256>>>(x, Ahi, Alo);

    uint32_t id256 = mk_idesc(256), id128 = mk_idesc(128);
    dim3 gg((MTOT + 127) / 128, 2);  // (391, 2)
    int gs = (MTOT + 7) / 8;         // 6250
    size_t shm = 197632;

    // Exactly one of k_gemm_tc / k_gemm_fb has a body in the loaded image.
    auto gemm = [&](int K, const __nv_bfloat16* bh, const __nv_bfloat16* bl,
                    const float* bias, int Nout, uint32_t idesc) {
        k_gemm_tc<<<gg, 256, shm>>>(Ahi, Alo, K, bh, bl, bias, Nout, idesc, yh, yx);
        k_gemm_fb<<<gg, 256>>>(Ahi, Alo, K, bh, bl, bias, Nout, idesc, yh, yx);
    };

    // L1: K=128, Nout=256
    gemm(128, Wth, Wtl, b1, 256, id256);
    k_aggact<8, 1><<<gs, 256>>>(yh, yx, 256, Ahi, Alo, nullptr);
    // L2-4: K=256, Nout=256
    for (int l = 0; l < 3; l++) {
        gemm(256, Wth + 65536, Wtl + 65536, b2, 256, id256);
        k_aggact<8, 1><<<gs, 256>>>(yh, yx, 256, Ahi, Alo, nullptr);
    }
    // L5: K=256, Nout=128, final fp32 out, no activation
    gemm(256, Wth + 196608, Wtl + 196608, b3, 128, id128);
    k_aggact<4, 0><<<gs, 256>>>(yh, yx, 128, nullptr, nullptr, out);
}

// round 5
// speedup vs baseline: 2.9534x; 1.3842x over previous
#include <cuda_runtime.h>
#include <cuda_bf16.h>
#include <cuda_fp16.h>
#include <stdint.h>
#include <math.h>

#define MTOT 50000
#define NE   800000

#if defined(__CUDA_ARCH_FEAT_SM103_ALL) || defined(__CUDA_ARCH_FEAT_SM100_ALL) || \
    defined(__CUDA_ARCH_FEAT_SM101_ALL) || defined(__CUDA_ARCH_FEAT_SM110_ALL)
#define TC_OK 1
#else
#define TC_OK 0
#endif

// ---------------- device scratch (no cudaMalloc) ----------------------------
__device__ __align__(16) __half g_act[(size_t)MTOT * 256];
__device__ __align__(16) float  g_yh[(size_t)MTOT * 256];
__device__ __align__(16) __half g_yx[(size_t)MTOT * 256];
__device__ __align__(16) __half g_Whi[262144];
__device__ __align__(16) __half g_Wlo[262144];
__device__ float g_dinv[MTOT];
__device__ int   g_deg[MTOT];
__device__ int   g_off[MTOT + 1];
__device__ int   g_cur[MTOT];
__device__ int   g_csrc[NE];
__device__ int   g_bsum[64];

// ---------------- small helpers ---------------------------------------------
__device__ __forceinline__ uint32_t smem_u32(const void* p) {
    uint32_t a;
    asm("{ .reg .u64 t; cvta.to.shared.u64 t, %1; cvt.u32.u64 %0, t; }" : "=r"(a) : "l"(p));
    return a;
}
__device__ __forceinline__ bool elect1() {
    uint32_t p;
    asm volatile("{\n\t.reg .pred p;\n\telect.sync _|p, 0xFFFFFFFF;\n\tselp.b32 %0,1,0,p;\n\t}" : "=r"(p));
    return p != 0;
}
__device__ __forceinline__ void mbar_init(uint32_t mbar, uint32_t cnt) {
    asm volatile("mbarrier.init.shared.b64 [%0], %1;" :: "r"(mbar), "r"(cnt) : "memory");
}
__device__ __forceinline__ void mbar_wait(uint32_t mbar, uint32_t parity) {
    uint32_t done;
    asm volatile("{\n\t.reg .pred p;\n\tmbarrier.try_wait.parity.acquire.cta.shared::cta.b64 p, [%1], %2;\n\tselp.b32 %0,1,0,p;\n\t}"
                 : "=r"(done) : "r"(mbar), "r"(parity) : "memory");
    if (!done) {
        asm volatile("{\n\t.reg .pred P1;\nWL_%=:\n\tmbarrier.try_wait.parity.acquire.cta.shared::cta.b64 P1, [%0], %1, 0x989680;\n\t@P1 bra.uni WD_%=;\n\tbra.uni WL_%=;\nWD_%=:\n\t}"
                     :: "r"(mbar), "r"(parity) : "memory");
    }
}
__device__ __forceinline__ float tanha(float x) {
    float y; asm("tanh.approx.f32 %0, %1;" : "=f"(y) : "f"(x)); return y;
}
__device__ __forceinline__ uint32_t pkh2(float a, float b) {
    __half2 h = __floats2half2_rn(a, b);
    return *reinterpret_cast<uint32_t*>(&h);
}

#if TC_OK
__device__ __forceinline__ uint64_t mk_desc(uint32_t addr) {
    // SW128, version=1(Blackwell), SBO=64, LBO=1, start=addr>>4
    return 0x4000404000010000ULL | ((uint64_t)(addr >> 4) & 0x3FFF);
}
__device__ __forceinline__ void mma_ss_f16(uint32_t d, uint64_t ad, uint64_t bd,
                                           uint32_t idesc, uint32_t en) {
    asm volatile("{\n\t.reg .pred p;\n\tsetp.ne.u32 p, %4, 0;\n\t"
                 "tcgen05.mma.cta_group::1.kind::f16 [%0], %1, %2, %3, {%5,%5,%5,%5}, p;\n\t}"
                 :: "r"(d), "l"(ad), "l"(bd), "r"(idesc), "r"(en), "r"(0u) : "memory");
}
#define LDTM32(r, addr) \
    asm volatile("tcgen05.ld.sync.aligned.32x32b.x32.b32 " \
        "{%0,%1,%2,%3,%4,%5,%6,%7,%8,%9,%10,%11,%12,%13,%14,%15," \
        "%16,%17,%18,%19,%20,%21,%22,%23,%24,%25,%26,%27,%28,%29,%30,%31}, [%32];" \
        : "=r"((r)[0]),"=r"((r)[1]),"=r"((r)[2]),"=r"((r)[3]),"=r"((r)[4]),"=r"((r)[5]),"=r"((r)[6]),"=r"((r)[7]), \
          "=r"((r)[8]),"=r"((r)[9]),"=r"((r)[10]),"=r"((r)[11]),"=r"((r)[12]),"=r"((r)[13]),"=r"((r)[14]),"=r"((r)[15]), \
          "=r"((r)[16]),"=r"((r)[17]),"=r"((r)[18]),"=r"((r)[19]),"=r"((r)[20]),"=r"((r)[21]),"=r"((r)[22]),"=r"((r)[23]), \
          "=r"((r)[24]),"=r"((r)[25]),"=r"((r)[26]),"=r"((r)[27]),"=r"((r)[28]),"=r"((r)[29]),"=r"((r)[30]),"=r"((r)[31]) \
        : "r"(addr))
#endif

// ---------------- CSR build (parallel scan) ----------------------------------
__global__ void k_zero_deg() {
    int i = blockIdx.x * blockDim.x + threadIdx.x;
    if (i < MTOT) g_deg[i] = 0;
}
__global__ void k_count(const int* __restrict__ dst) {
    int e = blockIdx.x * blockDim.x + threadIdx.x;
    if (e < NE) atomicAdd(&g_deg[dst[e]], 1);
}
__global__ void k_scan1() {
    __shared__ int sh[1024];
    int t = threadIdx.x;
    int i = blockIdx.x * 1024 + t;
    int v = (i < MTOT) ? g_deg[i] : 0;
    sh[t] = v;
    __syncthreads();
    for (int ofs = 1; ofs < 1024; ofs <<= 1) {
        int x = (t >= ofs) ? sh[t - ofs] : 0;
        __syncthreads();
        sh[t] += x;
        __syncthreads();
    }
    if (i < MTOT) g_off[i] = sh[t] - v;
    if (t == 1023) g_bsum[blockIdx.x] = sh[1023];
}
__global__ void k_scan2(int nblk) {
    __shared__ int sh[64];
    int t = threadIdx.x;
    int v = (t < nblk) ? g_bsum[t] : 0;
    sh[t] = v;
    __syncthreads();
    for (int ofs = 1; ofs < 64; ofs <<= 1) {
        int x = (t >= ofs) ? sh[t - ofs] : 0;
        __syncthreads();
        sh[t] += x;
        __syncthreads();
    }
    if (t < nblk) g_bsum[t] = sh[t] - v;
}
__global__ void k_scan3() {
    int i = blockIdx.x * 1024 + threadIdx.x;
    if (i < MTOT) {
        int o = g_off[i] + g_bsum[i >> 10];
        g_off[i] = o;
        g_cur[i] = o;
        int d = g_deg[i];
        g_dinv[i] = (d > 0) ? rsqrtf((float)d) : 0.0f;
    }
    if (i == 0) g_off[MTOT] = NE;
}
__global__ void k_scatter(const int* __restrict__ src, const int* __restrict__ dst) {
    int e = blockIdx.x * blockDim.x + threadIdx.x;
    if (e < NE) {
        int p = atomicAdd(&g_cur[dst[e]], 1);
        g_csrc[p] = src[e];
    }
}

// ---------------- converters ------------------------------------------------
// W (2F, N) -> transposed halves [Wh | Wx], each (N, F), fp16 hi/lo.
__global__ void k_convW2(const float* __restrict__ W, int F, int N,
                         __half* __restrict__ oh, __half* __restrict__ ol) {
    int idx = blockIdx.x * blockDim.x + threadIdx.x;
    if (idx >= 2 * F * N) return;
    int k2 = idx / N, n = idx % N;
    int half = (k2 >= F);
    int k = k2 - half * F;
    float v = W[(size_t)k2 * N + n];
    __half h = __float2half_rn(v);
    size_t o = (size_t)half * N * F + (size_t)n * F + k;
    oh[o] = h;
    ol[o] = __float2half_rn(v - __half2float(h));
}

__global__ void k_convX(const float* __restrict__ x, __half* __restrict__ act) {
    int idx = blockIdx.x * blockDim.x + threadIdx.x;
    if (idx >= MTOT * 32) return;
    int m = idx >> 5, c4 = (idx & 31) << 2;
    float4 v = *reinterpret_cast<const float4*>(x + (size_t)m * 128 + c4);
    uint2 p;
    p.x = pkh2(v.x, v.y);
    p.y = pkh2(v.z, v.w);
    *reinterpret_cast<uint2*>((char*)act + ((size_t)m * 128 + c4) * 2) = p;
}

// ---------------- aggregation + activation ----------------------------------
// h' = tanh(yh - dinv_n * sum_j yx[j]); yx already has dinv_j folded in.
// ACT=1: write fp16 activation. ACT=0: write fp32 (final output).
template <int CPL, int ACT>
__global__ void k_aggact(const float* __restrict__ yh, const __half* __restrict__ yx,
                         int Nout, __half* __restrict__ oact, float* __restrict__ of32) {
    int node = blockIdx.x * 8 + (threadIdx.x >> 5);
    if (node >= MTOT) return;
    int lane = threadIdx.x & 31;
    int col = lane * CPL;
    float acc[CPL];
#pragma unroll
    for (int i = 0; i < CPL; i++) acc[i] = 0.f;
    int e0 = g_off[node], e1 = g_off[node + 1];
    const char* yxb = (const char*)yx;
    int e = e0;
    for (; e + 2 <= e1; e += 2) {
        int j0 = g_csrc[e], j1 = g_csrc[e + 1];
        if constexpr (CPL == 8) {
            uint4 p0 = *reinterpret_cast<const uint4*>(yxb + ((size_t)j0 * Nout + col) * 2);
            uint4 p1 = *reinterpret_cast<const uint4*>(yxb + ((size_t)j1 * Nout + col) * 2);
            uint32_t w0[4] = {p0.x, p0.y, p0.z, p0.w};
            uint32_t w1[4] = {p1.x, p1.y, p1.z, p1.w};
#pragma unroll
            for (int q = 0; q < 4; q++) {
                float2 f0 = __half22float2(*reinterpret_cast<__half2*>(&w0[q]));
                float2 f1 = __half22float2(*reinterpret_cast<__half2*>(&w1[q]));
                acc[2 * q]     += f0.x + f1.x;
                acc[2 * q + 1] += f0.y + f1.y;
            }
        } else {
            uint2 p0 = *reinterpret_cast<const uint2*>(yxb + ((size_t)j0 * Nout + col) * 2);
            uint2 p1 = *reinterpret_cast<const uint2*>(yxb + ((size_t)j1 * Nout + col) * 2);
            uint32_t w0[2] = {p0.x, p0.y};
            uint32_t w1[2] = {p1.x, p1.y};
#pragma unroll
            for (int q = 0; q < 2; q++) {
                float2 f0 = __half22float2(*reinterpret_cast<__half2*>(&w0[q]));
                float2 f1 = __half22float2(*reinterpret_cast<__half2*>(&w1[q]));
                acc[2 * q]     += f0.x + f1.x;
                acc[2 * q + 1] += f0.y + f1.y;
            }
        }
    }
    if (e < e1) {
        int j0 = g_csrc[e];
        if constexpr (CPL == 8) {
            uint4 p0 = *reinterpret_cast<const uint4*>(yxb + ((size_t)j0 * Nout + col) * 2);
            uint32_t w0[4] = {p0.x, p0.y, p0.z, p0.w};
#pragma unroll
            for (int q = 0; q < 4; q++) {
                float2 f0 = __half22float2(*reinterpret_cast<__half2*>(&w0[q]));
                acc[2 * q] += f0.x; acc[2 * q + 1] += f0.y;
            }
        } else {
            uint2 p0 = *reinterpret_cast<const uint2*>(yxb + ((size_t)j0 * Nout + col) * 2);
            uint32_t w0[2] = {p0.x, p0.y};
#pragma unroll
            for (int q = 0; q < 2; q++) {
                float2 f0 = __half22float2(*reinterpret_cast<__half2*>(&w0[q]));
                acc[2 * q] += f0.x; acc[2 * q + 1] += f0.y;
            }
        }
    }
    float dv = g_dinv[node];
    float v[CPL];
#pragma unroll
    for (int i = 0; i < CPL; i += 4) {
        float4 y = *reinterpret_cast<const float4*>(yh + (size_t)node * Nout + col + i);
        v[i + 0] = y.x - dv * acc[i + 0];
        v[i + 1] = y.y - dv * acc[i + 1];
        v[i + 2] = y.z - dv * acc[i + 2];
        v[i + 3] = y.w - dv * acc[i + 3];
    }
    if constexpr (ACT) {
#pragma unroll
        for (int i = 0; i < CPL; i++) v[i] = tanha(v[i]);
        size_t wo = ((size_t)node * Nout + col) * 2;
        if constexpr (CPL == 8) {
            uint4 p;
            p.x = pkh2(v[0], v[1]); p.y = pkh2(v[2], v[3]);
            p.z = pkh2(v[4], v[5]); p.w = pkh2(v[6], v[7]);
            *reinterpret_cast<uint4*>((char*)oact + wo) = p;
        } else {
            uint2 p;
            p.x = pkh2(v[0], v[1]); p.y = pkh2(v[2], v[3]);
            *reinterpret_cast<uint2*>((char*)oact + wo) = p;
        }
    } else {
#pragma unroll
        for (int i = 0; i < CPL; i += 4) {
            float4 o = make_float4(v[i], v[i + 1], v[i + 2], v[i + 3]);
            *reinterpret_cast<float4*>(of32 + (size_t)node * Nout + col + i) = o;
        }
    }
}

// ---------------- tcgen05 dual-output fp16 GEMM ------------------------------
// One CTA = 128 rows; computes BOTH outputs in one pass over A:
//   yh = act@Wh + b (fp32, TMEM cols [0,256))
//   yx = dinv_m * (act@Wx) (fp16, TMEM cols [256,512))
// Stages: s = (kc, out); per stage: fill A (out==0) + B(hi,lo of one output),
// 2 MMA products (A@Bhi + A@Blo), 2-buffer pipeline with per-stage commits.
// SMEM: A slots 2x16KB @0/@16K; B stage bufs 2x64KB @32K/@96K (hi then lo).
__global__ void __launch_bounds__(256, 1) k_gemm_tc(
    const __half* __restrict__ act, int K,
    const __half* __restrict__ Whi, const __half* __restrict__ Wlo,
    const float* __restrict__ bias, int Nout, uint32_t idesc,
    float* __restrict__ yh, __half* __restrict__ yx)
{
#if TC_OK
    extern __shared__ char smraw[];
    __shared__ __align__(16) uint32_t ctrl[6];  // [0]=tmem ptr, +8/+16 = mbar x2
    int tid = threadIdx.x, wid = tid >> 5;
    uint32_t cu = smem_u32(ctrl);

    if (wid == 0) {
        asm volatile("tcgen05.alloc.cta_group::1.sync.aligned.shared::cta.b32 [%0], %1;"
                     :: "r"(cu), "r"(512u) : "memory");
        asm volatile("tcgen05.relinquish_alloc_permit.cta_group::1.sync.aligned;");
    }
    if (tid == 0) { mbar_init(cu + 8, 1); mbar_init(cu + 16, 1); }
    __syncthreads();
    uint32_t tmem;
    asm("ld.shared.b32 %0, [%1];" : "=r"(tmem) : "r"(cu));

    uint32_t raw = smem_u32(smraw);
    uint32_t sb = (raw + 1023) & ~1023u;
    char* sm = smraw + (sb - raw);

    int m0 = blockIdx.x * 128;
    const char* Ab = (const char*)act;
    int NS = (K >> 6) * 2;
    int nbB = Nout << 3;        // uint4 elements per B part tile
    int loOfs = Nout << 7;      // bytes: Nout*128 (hi tile size)

    for (int s = 0; s < NS; s++) {
        int kc = s >> 1, out = s & 1, buf = s & 1;
        char* bst = sm + 32768 + buf * 65536;
        uint32_t bstu = sb + 32768 + buf * 65536;
        if (s >= 2) mbar_wait(cu + 8 + buf * 8, ((s >> 1) - 1) & 1);

        if (out == 0) {
            // A tile for chunk kc: 128 rows x 64 fp16 -> slot kc&1
            char* ast = sm + (kc & 1) * 16384;
            for (int i = tid; i < 1024; i += 256) {
                int row = i >> 3, c = i & 7;
                int m = m0 + row;
                uint4 v = make_uint4(0, 0, 0, 0);
                if (m < MTOT)
                    v = *reinterpret_cast<const uint4*>(Ab + ((size_t)m * K + (kc << 6) + (c << 3)) * 2);
                uint32_t bo = (row << 7) + (c << 4);
                uint32_t so = bo ^ ((bo >> 3) & 0x70);
                *reinterpret_cast<uint4*>(ast + so) = v;
            }
        }
        // B tiles (hi+lo) for this output's chunk kc
        {
            size_t wofs = (size_t)out * Nout * K;
            const char* Bh = (const char*)(Whi + wofs);
            const char* Bl = (const char*)(Wlo + wofs);
            for (int i = tid; i < nbB; i += 256) {
                int n = i >> 3, c = i & 7;
                size_t go = ((size_t)n * K + (kc << 6) + (c << 3)) * 2;
                uint4 vh = *reinterpret_cast<const uint4*>(Bh + go);
                uint4 vl = *reinterpret_cast<const uint4*>(Bl + go);
                uint32_t bo = (n << 7) + (c << 4);
                uint32_t so = bo ^ ((bo >> 3) & 0x70);
                *reinterpret_cast<uint4*>(bst + so) = vh;
                *reinterpret_cast<uint4*>(bst + loOfs + so) = vl;
            }
        }
        asm volatile("fence.proxy.async.shared::cta;" ::: "memory");
        __syncthreads();

        if (wid == 0 && elect1()) {
            uint64_t dA  = mk_desc(sb + (kc & 1) * 16384);
            uint64_t dBh = mk_desc(bstu);
            uint64_t dBl = mk_desc(bstu + loOfs);
            uint32_t D = tmem + out * 256;
#pragma unroll
            for (int k = 0; k < 4; k++) {
                uint64_t o = (uint64_t)(k * 2);
                mma_ss_f16(D, dA + o, dBh + o, idesc, (uint32_t)((kc | k) != 0));
                mma_ss_f16(D, dA + o, dBl + o, idesc, 1u);
            }
            asm volatile("tcgen05.commit.cta_group::1.mbarrier::arrive::one.shared::cluster.b64 [%0];"
                         :: "r"(cu + 8 + buf * 8) : "memory");
        }
    }

    mbar_wait(cu + 8,  ((NS - 2) >> 1) & 1);
    mbar_wait(cu + 16, ((NS - 1) >> 1) & 1);
    asm volatile("tcgen05.fence::after_thread_sync;" ::: "memory");

    // epilogue: wg0 -> yh, wg1 -> yx; warp%4 = TMEM subpartition (rows)
    int lane = tid & 31, sub = wid & 3, wg = wid >> 2;
    int m = m0 + sub * 32 + lane;
    int niter = Nout >> 5;
    uint32_t base = tmem + wg * 256;
    for (int cc = 0; cc < niter; cc++) {
        uint32_t r[32];
        LDTM32(r, base + cc * 32);
        asm volatile("tcgen05.wait::ld.sync.aligned;" ::: "memory");
        if (m < MTOT) {
            int nb = cc * 32;
            if (wg == 0) {
                float4* dp = reinterpret_cast<float4*>(yh + (size_t)m * Nout + nb);
#pragma unroll
                for (int q = 0; q < 8; q++) {
                    float4 v;
                    v.x = __uint_as_float(r[q * 4 + 0]) + bias[nb + q * 4 + 0];
                    v.y = __uint_as_float(r[q * 4 + 1]) + bias[nb + q * 4 + 1];
                    v.z = __uint_as_float(r[q * 4 + 2]) + bias[nb + q * 4 + 2];
                    v.w = __uint_as_float(r[q * 4 + 3]) + bias[nb + q * 4 + 3];
                    dp[q] = v;
                }
            } else {
                float dv = g_dinv[m];
                uint32_t hp[16];
#pragma unroll
                for (int q = 0; q < 16; q++)
                    hp[q] = pkh2(dv * __uint_as_float(r[2 * q]),
                                 dv * __uint_as_float(r[2 * q + 1]));
                uint4* dp = reinterpret_cast<uint4*>((char*)yx + ((size_t)m * Nout + nb) * 2);
#pragma unroll
                for (int q = 0; q < 4; q++)
                    dp[q] = make_uint4(hp[4 * q], hp[4 * q + 1], hp[4 * q + 2], hp[4 * q + 3]);
            }
        }
    }
    __syncthreads();
    if (wid == 0) {
        asm volatile("tcgen05.dealloc.cta_group::1.sync.aligned.b32 %0, %1;"
                     :: "r"(tmem), "r"(512u));
    }
#endif  // TC_OK
}

// ---------------- SIMT fallback GEMM (non-"a" passes only) -------------------
__global__ void __launch_bounds__(256) k_gemm_fb(
    const __half* __restrict__ act, int K,
    const __half* __restrict__ Whi, const __half* __restrict__ Wlo,
    const float* __restrict__ bias, int Nout, uint32_t idesc,
    float* __restrict__ yh, __half* __restrict__ yx)
{
#if !TC_OK
    __shared__ float As[16][132];
    __shared__ float Bs[16][128];
    int tid = threadIdx.x;
    int tx = tid & 15, ty = tid >> 4;
    int m0 = blockIdx.x * 128;
    size_t hofs = (size_t)blockIdx.y * Nout * K;
    const __half* Bh = Whi + hofs;
    const __half* Bl = Wlo + hofs;

    for (int n0 = 0; n0 < Nout; n0 += 128) {
        float acc[8][8];
#pragma unroll
        for (int i = 0; i < 8; i++)
#pragma unroll
            for (int j = 0; j < 8; j++) acc[i][j] = 0.f;

        for (int k0 = 0; k0 < K; k0 += 16) {
            for (int i = tid; i < 2048; i += 256) {
                int r = i >> 4, k = i & 15;
                int m = m0 + r;
                As[k][r] = (m < MTOT) ? __half2float(act[(size_t)m * K + k0 + k]) : 0.f;
            }
            for (int i = tid; i < 2048; i += 256) {
                int r = i >> 4, k = i & 15;
                size_t o = (size_t)(n0 + r) * K + k0 + k;
                Bs[k][r] = __half2float(Bh[o]) + __half2float(Bl[o]);
            }
            __syncthreads();
#pragma unroll
            for (int k = 0; k < 16; k++) {
                float a[8], b[8];
#pragma unroll
                for (int i = 0; i < 8; i++) a[i] = As[k][ty * 8 + i];
#pragma unroll
                for (int j = 0; j < 8; j++) b[j] = Bs[k][tx * 8 + j];
#pragma unroll
                for (int i = 0; i < 8; i++)
#pragma unroll
                    for (int j = 0; j < 8; j++) acc[i][j] += a[i] * b[j];
            }
            __syncthreads();
        }

#pragma unroll
        for (int i = 0; i < 8; i++) {
            int m = m0 + ty * 8 + i;
            if (m >= MTOT) continue;
            float dv = g_dinv[m];
#pragma unroll
            for (int j = 0; j < 8; j++) {
                int n = n0 + tx * 8 + j;
                if (blockIdx.y == 0) yh[(size_t)m * Nout + n] = acc[i][j] + bias[n];
                else                 yx[(size_t)m * Nout + n] = __float2half_rn(dv * acc[i][j]);
            }
        }
        __syncthreads();
    }
#endif  // !TC_OK
}

// ---------------- launch -----------------------------------------------------
static inline uint32_t mk_idesc(int N) {
    // dtype=F32, atype=btype=FP16(0), M=128
    return (1u << 4) | ((uint32_t)(N / 8) << 17) | (8u << 24);
}

extern "C" void kernel_launch(void* const* d_in, const int* in_sizes, int n_in,
                              void* d_out, int out_size) {
    const float* x   = (const float*)d_in[0];
    const int*   src = (const int*)d_in[1];
    const int*   dst = (const int*)d_in[2];
    const float* W1  = (const float*)d_in[3];
    const float* b1  = (const float*)d_in[4];
    const float* W2  = (const float*)d_in[5];
    const float* b2  = (const float*)d_in[6];
    const float* W3  = (const float*)d_in[7];
    const float* b3  = (const float*)d_in[8];
    float* out = (float*)d_out;

    void* p;
    cudaGetSymbolAddress(&p, g_act);  __half* act = (__half*)p;
    cudaGetSymbolAddress(&p, g_yh);   float*  yh  = (float*)p;
    cudaGetSymbolAddress(&p, g_yx);   __half* yx  = (__half*)p;
    cudaGetSymbolAddress(&p, g_Whi);  __half* Whi = (__half*)p;
    cudaGetSymbolAddress(&p, g_Wlo);  __half* Wlo = (__half*)p;

    cudaFuncSetAttribute(k_gemm_tc, cudaFuncAttributeMaxDynamicSharedMemorySize, 165888);

    // CSR build (parallel scan)
    int nblk = (MTOT + 1023) / 1024;  // 49
    k_zero_deg<<<(MTOT + 255) / 256, 256>>>();
    k_count<<<(NE + 255) / 256, 256>>>(dst);
    k_scan1<<<nblk, 1024>>>();
    k_scan2<<<1, 64>>>(nblk);
    k_scan3<<<nblk, 1024>>>();
    k_scatter<<<(NE + 255) / 256, 256>>>(src, dst);

    // weight + input conversion
    // blob: W1 @0 (2*256*128); W2 @65536 (2*256*256); W3 @196608 (2*128*256)
    k_convW2<<<(256 * 256 + 255) / 256, 256>>>(W1, 128, 256, Whi, Wlo);
    k_convW2<<<(512 * 256 + 255) / 256, 256>>>(W2, 256, 256, Whi + 65536, Wlo + 65536);
    k_convW2<<<(512 * 128 + 255) / 256, 256>>>(W3, 256, 128, Whi + 196608, Wlo + 196608);
    k_convX<<<(MTOT * 32 + 255) / 256, 256>>>(x, act);

    uint32_t id256 = mk_idesc(256), id128 = mk_idesc(128);
    int gg = (MTOT + 127) / 128;     // 391
    dim3 ggfb(gg, 2);
    int gs = (MTOT + 7) / 8;         // 6250
    size_t shm = 165888;

    // Exactly one of k_gemm_tc / k_gemm_fb has a body in the loaded image.
    auto gemm = [&](int K, const __half* bh, const __half* bl,
                    const float* bias, int Nout, uint32_t idesc) {
        k_gemm_tc<<<gg, 256, shm>>>(act, K, bh, bl, bias, Nout, idesc, yh, yx);
        k_gemm_fb<<<ggfb, 256>>>(act, K, bh, bl, bias, Nout, idesc, yh, yx);
    };

    // L1: K=128, Nout=256
    gemm(128, Whi, Wlo, b1, 256, id256);
    k_aggact<8, 1><<<gs, 256>>>(yh, yx, 256, act, nullptr);
    // L2-4: K=256, Nout=256 (shared W2)
    for (int l = 0; l < 3; l++) {
        gemm(256, Whi + 65536, Wlo + 65536, b2, 256, id256);
        k_aggact<8, 1><<<gs, 256>>>(yh, yx, 256, act, nullptr);
    }
    // L5: K=256, Nout=128; final: out = yh - dv*sum(yx), no tanh
    gemm(256, Whi + 196608, Wlo + 196608, b3, 128, id128);
    k_aggact<4, 0><<<gs, 256>>>(yh, yx, 128, nullptr, out);
}